// round 11
// baseline (speedup 1.0000x reference)
#include <cuda_runtime.h>
#include <cuda_bf16.h>
#include <cstdint>

#define B_    2
#define S_    2048
#define D_    1024
#define H_    16
#define KV_   4
#define QKB_  16
#define VB_   32
#define NROWS (B_*S_)        // 4096

// Scratch (device globals: allocation-free)
__device__ float g_q[NROWS * H_  * QKB_];   // [row][256]  col = h*16+d  (pre-scaled by 2)
__device__ float g_k[NROWS * KV_ * QKB_];   // [row][64]   col = kv*16+d
__device__ float g_v[NROWS * KV_ * VB_];    // [row][128]  col = kv*32+d
__device__ float g_sumk[NROWS * KV_];       // [row][4]
__device__ float g_vh[NROWS * H_ * VB_];    // [row][512]  col = h*32+d

__device__ __forceinline__ float sigmoidf_(float x) {
    return 1.0f / (1.0f + __expf(-x));
}

// split fp32 -> (hi bf16, lo bf16) packed pairs
__device__ __forceinline__ void split2(float x0, float x1, uint32_t& hp, uint32_t& lp) {
    __nv_bfloat16 h0 = __float2bfloat16(x0);
    __nv_bfloat16 h1 = __float2bfloat16(x1);
    __nv_bfloat16 l0 = __float2bfloat16(x0 - __bfloat162float(h0));
    __nv_bfloat16 l1 = __float2bfloat16(x1 - __bfloat162float(h1));
    hp = (uint32_t)__bfloat16_as_ushort(h0) | ((uint32_t)__bfloat16_as_ushort(h1) << 16);
    lp = (uint32_t)__bfloat16_as_ushort(l0) | ((uint32_t)__bfloat16_as_ushort(l1) << 16);
}

// Legacy tensor-core path (valid on plain sm_103 target): m16n8k16 bf16 mma
__device__ __forceinline__ void mma16816(float* c, const uint32_t* a, const uint32_t* b) {
    asm volatile(
        "mma.sync.aligned.m16n8k16.row.col.f32.bf16.bf16.f32 "
        "{%0,%1,%2,%3}, {%4,%5,%6,%7}, {%8,%9}, {%0,%1,%2,%3};"
        : "+f"(c[0]), "+f"(c[1]), "+f"(c[2]), "+f"(c[3])
        : "r"(a[0]), "r"(a[1]), "r"(a[2]), "r"(a[3]), "r"(b[0]), "r"(b[1]));
}

// ---------------------------------------------------------------------------
// Kernel 1: fused QKV projection + sigmoid (fp32, unchanged this round)
// ---------------------------------------------------------------------------
__global__ __launch_bounds__(256) void qkv_kernel(
    const float* __restrict__ x,  const float* __restrict__ Wq,
    const float* __restrict__ Wk, const float* __restrict__ Wv)
{
    __shared__ float As[16][132];
    __shared__ float Bs[16][64];

    const int n0 = blockIdx.x * 64;
    const int m0 = blockIdx.y * 128;

    const float* W; int ldw, c0; float* Out; int ldo, oc0;
    if (n0 < 256)      { W = Wq; ldw = 256; c0 = n0;       Out = g_q; ldo = 256; oc0 = n0; }
    else if (n0 < 320) { W = Wk; ldw = 64;  c0 = 0;        Out = g_k; ldo = 64;  oc0 = 0; }
    else               { W = Wv; ldw = 128; c0 = n0 - 320; Out = g_v; ldo = 128; oc0 = n0 - 320; }

    const int tid = threadIdx.x;
    const int tx = tid & 15;
    const int ty = tid >> 4;

    float acc[8][4] = {};

    for (int k0 = 0; k0 < D_; k0 += 16) {
        #pragma unroll
        for (int it = 0; it < 2; it++) {
            int e = tid * 2 + it;
            int r = e >> 2, c4 = (e & 3) * 4;
            float4 va = *(const float4*)&x[(m0 + r) * D_ + k0 + c4];
            As[c4 + 0][r] = va.x; As[c4 + 1][r] = va.y;
            As[c4 + 2][r] = va.z; As[c4 + 3][r] = va.w;
        }
        {
            int r = tid >> 4, c4 = (tid & 15) * 4;
            *(float4*)&Bs[r][c4] = *(const float4*)&W[(k0 + r) * ldw + c0 + c4];
        }
        __syncthreads();
        #pragma unroll
        for (int k = 0; k < 16; k++) {
            float4 a0 = *(const float4*)&As[k][ty * 8];
            float4 a1 = *(const float4*)&As[k][ty * 8 + 4];
            float a[8] = {a0.x, a0.y, a0.z, a0.w, a1.x, a1.y, a1.z, a1.w};
            float4 vb = *(const float4*)&Bs[k][tx * 4];
            float b[4] = {vb.x, vb.y, vb.z, vb.w};
            #pragma unroll
            for (int i = 0; i < 8; i++)
                #pragma unroll
                for (int j = 0; j < 4; j++)
                    acc[i][j] = fmaf(a[i], b[j], acc[i][j]);
        }
        __syncthreads();
    }

    const float qscale = (n0 < 256) ? 2.0f : 1.0f;
    #pragma unroll
    for (int i = 0; i < 8; i++) {
        int row = m0 + ty * 8 + i;
        float4 o;
        o.x = qscale * sigmoidf_(acc[i][0]); o.y = qscale * sigmoidf_(acc[i][1]);
        o.z = qscale * sigmoidf_(acc[i][2]); o.w = qscale * sigmoidf_(acc[i][3]);
        *(float4*)&Out[row * ldo + oc0 + tx * 4] = o;
    }
}

// ---------------------------------------------------------------------------
// Kernel 2: per-(row,kv) sum of pk over QKB
// ---------------------------------------------------------------------------
__global__ void sumk_kernel() {
    int i = blockIdx.x * blockDim.x + threadIdx.x;
    if (i >= NROWS * KV_) return;
    int row = i >> 2, kv = i & 3;
    const float* p = &g_k[row * 64 + kv * 16];
    float s = 0.f;
    #pragma unroll
    for (int d = 0; d < 16; d++) s += p[d];
    g_sumk[i] = s;
}

// ---------------------------------------------------------------------------
// Kernel 3: streaming causal attention (fp32, unchanged this round)
// ---------------------------------------------------------------------------
__global__ __launch_bounds__(128) void attn_kernel() {
    __shared__ float sk[64][16];
    __shared__ float sv[64][32];
    __shared__ float ssum[64];

    const int qt = blockIdx.x, h = blockIdx.y, b = blockIdx.z;
    const int s   = qt * 128 + threadIdx.x;
    const int row = b * S_ + s;
    const int kv  = h >> 2;

    float pq[16];
    {
        const float4* qp = (const float4*)&g_q[row * (H_ * QKB_) + h * QKB_];
        #pragma unroll
        for (int i = 0; i < 4; i++) {
            float4 v = qp[i];
            pq[4*i] = v.x; pq[4*i+1] = v.y; pq[4*i+2] = v.z; pq[4*i+3] = v.w;
        }
    }

    float acc[32] = {};
    float den = 0.f;

    const int tfull = qt * 128;
    int t0 = 0;
    for (; t0 < tfull + 128; t0 += 64) {
        __syncthreads();
        {
            int e = threadIdx.x;
            #pragma unroll
            for (int it = 0; it < 2; it++, e += 128) {
                int r = e >> 2, c4 = (e & 3) * 4;
                *(float4*)&sk[r][c4] =
                    *(const float4*)&g_k[(b * S_ + t0 + r) * 64 + kv * 16 + c4];
            }
        }
        {
            int e = threadIdx.x;
            #pragma unroll
            for (int it = 0; it < 4; it++, e += 128) {
                int r = e >> 3, c4 = (e & 7) * 4;
                *(float4*)&sv[r][c4] =
                    *(const float4*)&g_v[(b * S_ + t0 + r) * 128 + kv * 32 + c4];
            }
        }
        if (threadIdx.x < 64)
            ssum[threadIdx.x] = g_sumk[(b * S_ + t0 + threadIdx.x) * 4 + kv];
        __syncthreads();

        if (t0 < tfull) {
            #pragma unroll 2
            for (int tt = 0; tt < 64; tt += 2) {
                const float4* kp0 = (const float4*)sk[tt];
                const float4* kp1 = (const float4*)sk[tt + 1];
                float dot0 = 0.f, dot1 = 0.f;
                #pragma unroll
                for (int i = 0; i < 4; i++) {
                    float4 k0 = kp0[i], k1 = kp1[i];
                    dot0 = fmaf(pq[4*i  ], k0.x, dot0);
                    dot1 = fmaf(pq[4*i  ], k1.x, dot1);
                    dot0 = fmaf(pq[4*i+1], k0.y, dot0);
                    dot1 = fmaf(pq[4*i+1], k1.y, dot1);
                    dot0 = fmaf(pq[4*i+2], k0.z, dot0);
                    dot1 = fmaf(pq[4*i+2], k1.z, dot1);
                    dot0 = fmaf(pq[4*i+3], k0.w, dot0);
                    dot1 = fmaf(pq[4*i+3], k1.w, dot1);
                }
                float w0 = __expf(dot0 - ssum[tt]);
                float w1 = __expf(dot1 - ssum[tt + 1]);
                den += w0 + w1;
                const float4* vp0 = (const float4*)sv[tt];
                const float4* vp1 = (const float4*)sv[tt + 1];
                #pragma unroll
                for (int i = 0; i < 8; i++) {
                    float4 v0 = vp0[i], v1 = vp1[i];
                    acc[4*i  ] = fmaf(w1, v1.x, fmaf(w0, v0.x, acc[4*i  ]));
                    acc[4*i+1] = fmaf(w1, v1.y, fmaf(w0, v0.y, acc[4*i+1]));
                    acc[4*i+2] = fmaf(w1, v1.z, fmaf(w0, v0.z, acc[4*i+2]));
                    acc[4*i+3] = fmaf(w1, v1.w, fmaf(w0, v0.w, acc[4*i+3]));
                }
            }
        } else {
            int nt = s - t0 + 1;
            if (nt > 64) nt = 64;
            for (int tt = 0; tt < nt; tt++) {
                const float4* kp = (const float4*)sk[tt];
                float dot = 0.f;
                #pragma unroll
                for (int i = 0; i < 4; i++) {
                    float4 kk = kp[i];
                    dot = fmaf(pq[4*i  ], kk.x, dot);
                    dot = fmaf(pq[4*i+1], kk.y, dot);
                    dot = fmaf(pq[4*i+2], kk.z, dot);
                    dot = fmaf(pq[4*i+3], kk.w, dot);
                }
                float w = __expf(dot - ssum[tt]);
                den += w;
                const float4* vp = (const float4*)sv[tt];
                #pragma unroll
                for (int i = 0; i < 8; i++) {
                    float4 vv = vp[i];
                    acc[4*i  ] = fmaf(w, vv.x, acc[4*i  ]);
                    acc[4*i+1] = fmaf(w, vv.y, acc[4*i+1]);
                    acc[4*i+2] = fmaf(w, vv.z, acc[4*i+2]);
                    acc[4*i+3] = fmaf(w, vv.w, acc[4*i+3]);
                }
            }
        }
    }

    float inv = 1.0f / den;
    float* op = &g_vh[row * (H_ * VB_) + h * VB_];
    #pragma unroll
    for (int i = 0; i < 8; i++) {
        *(float4*)&op[4*i] = make_float4(acc[4*i] * inv, acc[4*i+1] * inv,
                                         acc[4*i+2] * inv, acc[4*i+3] * inv);
    }
}

// ---------------------------------------------------------------------------
// Kernel 4: mma.sync bf16 split-precision GEMM (legacy tensor path, sm_103-safe)
// C[4096,1024] = blend(g_vh)[4096,512] @ Wo[512,1024]
// CTA tile 128x128, 8 warps (warp tile 32m x 64n), K-chunk 32 (2 mma k-steps).
// A/B staged in smem directly in mma fragment layout -> no ldmatrix needed:
//   A[kstep][mt(8)][lane(32)][reg(4)]  (LDS.128 per fragment)
//   B[kstep][nt(16)] padded to 66 u32  (LDS.64 per fragment)
// Split: D += Ah*Bh + Al*Bh + Ah*Bl  (per-product eps ~2^-17, fp32 accum).
// ---------------------------------------------------------------------------
__global__ __launch_bounds__(256) void out_tc_kernel(
    const float* __restrict__ Wo, const float* __restrict__ e0,
    const float* __restrict__ e1, float* __restrict__ out)
{
    __shared__ uint32_t sAh[2 * 8 * 32 * 4];     // 8 KB
    __shared__ uint32_t sAl[2 * 8 * 32 * 4];     // 8 KB
    __shared__ uint32_t sBh[2 * 16 * 66];        // 8.25 KB (padded: kills STS conflicts)
    __shared__ uint32_t sBl[2 * 16 * 66];

    const int tid  = threadIdx.x;
    const int warp = tid >> 5, lane = tid & 31;
    const int n0 = blockIdx.x * 128;
    const int m0 = blockIdx.y * 128;
    const int mw = warp & 3;          // m-band: rows mw*32 .. mw*32+31
    const int nw = warp >> 1 >> 1;    // n-band: cols nw*64 .. nw*64+63  (warp>>2)

    float c[2][8][4] = {};

    // staging roles (fixed per thread)
    const int am  = tid >> 1;         // A: m row 0..127
    const int aks = tid & 1;          // A: kstep 0/1
    const int bp  = tid >> 4;         // B: k-pair 0..15  (kk = 2*bp)
    const int bnb = (tid & 15) * 8;   // B: n base

    for (int ch = 0; ch < 16; ch++) {
        const int k0 = ch * 32;
        __syncthreads();              // previous chunk's reads done before overwrite

        // ---- stage A: blend(g_vh) 128 x 32 -> fragment layout ----
        {
            const float* ar = &g_vh[(size_t)(m0 + am) * 512 + k0 + aks * 16];
            const float* z0 = &e0[k0 + aks * 16];
            const float* z1 = &e1[k0 + aks * 16];
            const int mt = am >> 4;
            const int mh = (am >> 3) & 1;
            const int lbase = (am & 7) * 4;
            #pragma unroll
            for (int q = 0; q < 4; q++) {            // 4 float4 = 16 k
                float4 v  = *(const float4*)&ar[q * 4];
                float4 a0 = *(const float4*)&z0[q * 4];
                float4 a1 = *(const float4*)&z1[q * 4];
                float x0 = fmaf(a1.x - a0.x, v.x, a0.x);
                float x1 = fmaf(a1.y - a0.y, v.y, a0.y);
                float x2 = fmaf(a1.z - a0.z, v.z, a0.z);
                float x3 = fmaf(a1.w - a0.w, v.w, a0.w);
                // pairs (kk, kk+1) with kk = q*4 and q*4+2
                #pragma unroll
                for (int h = 0; h < 2; h++) {
                    int kk = q * 4 + h * 2;
                    uint32_t hp, lp;
                    if (h == 0) split2(x0, x1, hp, lp); else split2(x2, x3, hp, lp);
                    int reg    = ((kk >> 3) << 1) | mh;
                    int lane_t = lbase + ((kk & 7) >> 1);
                    int idx    = ((aks * 8 + mt) * 32 + lane_t) * 4 + reg;
                    sAh[idx] = hp; sAl[idx] = lp;
                }
            }
        }
        // ---- stage B: Wo 32 x 128 -> fragment layout ----
        {
            const float* r0 = &Wo[(size_t)(k0 + 2 * bp) * 1024 + n0 + bnb];
            const float* r1 = r0 + 1024;
            float4 x0a = *(const float4*)&r0[0], x0b = *(const float4*)&r0[4];
            float4 x1a = *(const float4*)&r1[0], x1b = *(const float4*)&r1[4];
            const int kkl  = (2 * bp) & 15;
            const int ks   = bp >> 3;
            const int reg  = kkl >> 3;
            const int ltk  = (kkl & 7) >> 1;
            float v0[8] = {x0a.x, x0a.y, x0a.z, x0a.w, x0b.x, x0b.y, x0b.z, x0b.w};
            float v1[8] = {x1a.x, x1a.y, x1a.z, x1a.w, x1b.x, x1b.y, x1b.z, x1b.w};
            #pragma unroll
            for (int j = 0; j < 8; j++) {
                int n = bnb + j;
                uint32_t hp, lp;
                split2(v0[j], v1[j], hp, lp);      // pair along k
                int idx = (ks * 16 + (n >> 3)) * 66 + ((n & 7) * 4 + ltk) * 2 + reg;
                sBh[idx] = hp; sBl[idx] = lp;
            }
        }
        __syncthreads();

        // ---- compute: 2 k-steps x 3 split passes ----
        #pragma unroll
        for (int ks = 0; ks < 2; ks++) {
            uint32_t ah[2][4], al[2][4], bh[8][2], bl[8][2];
            #pragma unroll
            for (int i = 0; i < 2; i++) {
                const uint4 v = *(const uint4*)&sAh[((ks * 8 + mw * 2 + i) * 32 + lane) * 4];
                ah[i][0] = v.x; ah[i][1] = v.y; ah[i][2] = v.z; ah[i][3] = v.w;
            }
            #pragma unroll
            for (int j = 0; j < 8; j++) {
                const uint2 v = *(const uint2*)&sBh[(ks * 16 + nw * 8 + j) * 66 + lane * 2];
                bh[j][0] = v.x; bh[j][1] = v.y;
            }
            #pragma unroll
            for (int i = 0; i < 2; i++)
                #pragma unroll
                for (int j = 0; j < 8; j++)
                    mma16816(c[i][j], ah[i], bh[j]);        // Ah*Bh

            #pragma unroll
            for (int i = 0; i < 2; i++) {
                const uint4 v = *(const uint4*)&sAl[((ks * 8 + mw * 2 + i) * 32 + lane) * 4];
                al[i][0] = v.x; al[i][1] = v.y; al[i][2] = v.z; al[i][3] = v.w;
            }
            #pragma unroll
            for (int i = 0; i < 2; i++)
                #pragma unroll
                for (int j = 0; j < 8; j++)
                    mma16816(c[i][j], al[i], bh[j]);        // Al*Bh

            #pragma unroll
            for (int j = 0; j < 8; j++) {
                const uint2 v = *(const uint2*)&sBl[(ks * 16 + nw * 8 + j) * 66 + lane * 2];
                bl[j][0] = v.x; bl[j][1] = v.y;
            }
            #pragma unroll
            for (int i = 0; i < 2; i++)
                #pragma unroll
                for (int j = 0; j < 8; j++)
                    mma16816(c[i][j], ah[i], bl[j]);        // Ah*Bl
        }
    }

    // ---- epilogue: fragment -> global ----
    const int g  = lane >> 2, tg = lane & 3;
    #pragma unroll
    for (int i = 0; i < 2; i++) {
        #pragma unroll
        for (int j = 0; j < 8; j++) {
            int r0 = m0 + (mw * 2 + i) * 16 + g;
            int cc = n0 + (nw * 8 + j) * 8 + tg * 2;
            *(float2*)&out[(size_t)r0 * 1024 + cc] = make_float2(c[i][j][0], c[i][j][1]);
            *(float2*)&out[(size_t)(r0 + 8) * 1024 + cc] = make_float2(c[i][j][2], c[i][j][3]);
        }
    }
}

// ---------------------------------------------------------------------------
extern "C" void kernel_launch(void* const* d_in, const int* in_sizes, int n_in,
                              void* d_out, int out_size)
{
    const float* x  = (const float*)d_in[0];
    const float* Wq = (const float*)d_in[1];
    const float* Wk = (const float*)d_in[2];
    const float* Wv = (const float*)d_in[3];
    const float* Wo = (const float*)d_in[4];
    const float* e0 = (const float*)d_in[5];
    const float* e1 = (const float*)d_in[6];
    float* out = (float*)d_out;

    qkv_kernel<<<dim3(7, 32), 256>>>(x, Wq, Wk, Wv);
    sumk_kernel<<<64, 256>>>();
    attn_kernel<<<dim3(S_ / 128, H_, B_), 128>>>();
    out_tc_kernel<<<dim3(8, 32), 256>>>(Wo, e0, e1, out);
}

// round 15
// speedup vs baseline: 2.7458x; 2.7458x over previous
#include <cuda_runtime.h>
#include <cuda_bf16.h>
#include <cstdint>

#define B_    2
#define S_    2048
#define D_    1024
#define H_    16
#define KV_   4
#define QKB_  16
#define VB_   32
#define NROWS (B_*S_)        // 4096

// Scratch (device globals: allocation-free)
__device__ float g_q[NROWS * H_  * QKB_];   // [row][256]  col = h*16+d  (pre-scaled by 2)
__device__ float g_k[NROWS * KV_ * QKB_];   // [row][64]   col = kv*16+d
__device__ float g_v[NROWS * KV_ * VB_];    // [row][128]  col = kv*32+d
__device__ float g_sumk[NROWS * KV_];       // [row][4]
__device__ float g_vh[NROWS * H_ * VB_];    // [row][512]  col = h*32+d

__device__ __forceinline__ float sigmoidf_(float x) {
    return 1.0f / (1.0f + __expf(-x));
}

// split fp32 -> (hi bf16, lo bf16) packed pairs (lo16 = first arg)
__device__ __forceinline__ void split2(float x0, float x1, uint32_t& hp, uint32_t& lp) {
    __nv_bfloat16 h0 = __float2bfloat16(x0);
    __nv_bfloat16 h1 = __float2bfloat16(x1);
    __nv_bfloat16 l0 = __float2bfloat16(x0 - __bfloat162float(h0));
    __nv_bfloat16 l1 = __float2bfloat16(x1 - __bfloat162float(h1));
    hp = (uint32_t)__bfloat16_as_ushort(h0) | ((uint32_t)__bfloat16_as_ushort(h1) << 16);
    lp = (uint32_t)__bfloat16_as_ushort(l0) | ((uint32_t)__bfloat16_as_ushort(l1) << 16);
}

// Legacy tensor path (valid on plain sm_103 target): m16n8k16 bf16 mma
__device__ __forceinline__ void mma16816(float* c, const uint32_t* a, const uint32_t* b) {
    asm volatile(
        "mma.sync.aligned.m16n8k16.row.col.f32.bf16.bf16.f32 "
        "{%0,%1,%2,%3}, {%4,%5,%6,%7}, {%8,%9}, {%0,%1,%2,%3};"
        : "+f"(c[0]), "+f"(c[1]), "+f"(c[2]), "+f"(c[3])
        : "r"(a[0]), "r"(a[1]), "r"(a[2]), "r"(a[3]), "r"(b[0]), "r"(b[1]));
}

// ---------------------------------------------------------------------------
// Kernel 1: fused QKV projection + sigmoid (fp32)
// ---------------------------------------------------------------------------
__global__ __launch_bounds__(256) void qkv_kernel(
    const float* __restrict__ x,  const float* __restrict__ Wq,
    const float* __restrict__ Wk, const float* __restrict__ Wv)
{
    __shared__ float As[16][132];
    __shared__ float Bs[16][64];

    const int n0 = blockIdx.x * 64;
    const int m0 = blockIdx.y * 128;

    const float* W; int ldw, c0; float* Out; int ldo, oc0;
    if (n0 < 256)      { W = Wq; ldw = 256; c0 = n0;       Out = g_q; ldo = 256; oc0 = n0; }
    else if (n0 < 320) { W = Wk; ldw = 64;  c0 = 0;        Out = g_k; ldo = 64;  oc0 = 0; }
    else               { W = Wv; ldw = 128; c0 = n0 - 320; Out = g_v; ldo = 128; oc0 = n0 - 320; }

    const int tid = threadIdx.x;
    const int tx = tid & 15;
    const int ty = tid >> 4;

    float acc[8][4] = {};

    for (int k0 = 0; k0 < D_; k0 += 16) {
        #pragma unroll
        for (int it = 0; it < 2; it++) {
            int e = tid * 2 + it;
            int r = e >> 2, c4 = (e & 3) * 4;
            float4 va = *(const float4*)&x[(m0 + r) * D_ + k0 + c4];
            As[c4 + 0][r] = va.x; As[c4 + 1][r] = va.y;
            As[c4 + 2][r] = va.z; As[c4 + 3][r] = va.w;
        }
        {
            int r = tid >> 4, c4 = (tid & 15) * 4;
            *(float4*)&Bs[r][c4] = *(const float4*)&W[(k0 + r) * ldw + c0 + c4];
        }
        __syncthreads();
        #pragma unroll
        for (int k = 0; k < 16; k++) {
            float4 a0 = *(const float4*)&As[k][ty * 8];
            float4 a1 = *(const float4*)&As[k][ty * 8 + 4];
            float a[8] = {a0.x, a0.y, a0.z, a0.w, a1.x, a1.y, a1.z, a1.w};
            float4 vb = *(const float4*)&Bs[k][tx * 4];
            float b[4] = {vb.x, vb.y, vb.z, vb.w};
            #pragma unroll
            for (int i = 0; i < 8; i++)
                #pragma unroll
                for (int j = 0; j < 4; j++)
                    acc[i][j] = fmaf(a[i], b[j], acc[i][j]);
        }
        __syncthreads();
    }

    const float qscale = (n0 < 256) ? 2.0f : 1.0f;   // fold 2*pq.pk into pq
    #pragma unroll
    for (int i = 0; i < 8; i++) {
        int row = m0 + ty * 8 + i;
        float4 o;
        o.x = qscale * sigmoidf_(acc[i][0]); o.y = qscale * sigmoidf_(acc[i][1]);
        o.z = qscale * sigmoidf_(acc[i][2]); o.w = qscale * sigmoidf_(acc[i][3]);
        *(float4*)&Out[row * ldo + oc0 + tx * 4] = o;
    }
}

// ---------------------------------------------------------------------------
// Kernel 2: per-(row,kv) sum of pk over QKB
// ---------------------------------------------------------------------------
__global__ void sumk_kernel() {
    int i = blockIdx.x * blockDim.x + threadIdx.x;
    if (i >= NROWS * KV_) return;
    int row = i >> 2, kv = i & 3;
    const float* p = &g_k[row * 64 + kv * 16];
    float s = 0.f;
    #pragma unroll
    for (int d = 0; d < 16; d++) s += p[d];
    g_sumk[i] = s;
}

// ---------------------------------------------------------------------------
// Kernel 3 (NEW): tensor-core causal attention.
// Per CTA: (q-tile 128, head, batch). 8 warps: mw=warp&3 (m-band 32 rows),
// nw=warp>>2 (t-band 64 keys). Per 128-key tile:
//   S = Q K^T  (m16n8k16, QKB=16 = one k-step, split-precision 3 passes)
//   w = exp(S - sumk[t]) in fragments (den accumulated from fp32 w -> exact)
//   numer += w V  (w repacked in-registers into A-fragments, split 3 passes)
// Cross-warp (nw) reduction once at the end via smem reuse.
// ---------------------------------------------------------------------------
__global__ __launch_bounds__(256) void attn_tc_kernel() {
    __shared__ __align__(16) char sm[25088];
    uint32_t* sKh = (uint32_t*)sm;          // [(j*32+lane)*2+breg] j=0..15
    uint32_t* sKl = sKh + 1024;
    uint32_t* sVh = sKl + 1024;             // [((ks*4+jv)*32+lane)*2+breg]
    uint32_t* sVl = sVh + 2048;
    float*    ssum = (float*)(sVl + 2048);  // [128]

    const int tid = threadIdx.x, warp = tid >> 5, lane = tid & 31;
    const int g = lane >> 2, tig = lane & 3;
    const int mw = warp & 3, nw = warp >> 2;
    const int qt = (S_ / 128 - 1) - blockIdx.x;   // heavy q-tiles launch first
    const int h = blockIdx.y, b = blockIdx.z;
    const int kv = h >> 2;
    const int m0 = qt * 128;

    // ---- Q fragments (held all kernel), split hi/lo ----
    uint32_t qh[2][4], ql[2][4];
    #pragma unroll
    for (int i = 0; i < 2; i++) {
        int r0 = m0 + mw * 32 + i * 16 + g;
        const float* q0 = &g_q[(size_t)(b * S_ + r0) * 256 + h * 16];
        const float* q1 = q0 + 8 * 256;
        split2(q0[2 * tig],     q0[2 * tig + 1], qh[i][0], ql[i][0]);
        split2(q1[2 * tig],     q1[2 * tig + 1], qh[i][1], ql[i][1]);
        split2(q0[2 * tig + 8], q0[2 * tig + 9], qh[i][2], ql[i][2]);
        split2(q1[2 * tig + 8], q1[2 * tig + 9], qh[i][3], ql[i][3]);
    }

    float num[2][4][4] = {};        // [i][jv][c]
    float den[2][2] = {};           // [i][row-half]

    const int KT = tid >> 1, KH = tid & 1;       // K staging: t-row, k-half
    const int Vtp = tid >> 2, Vvbq = (tid & 3) * 8;  // V staging: t-pair, vb-quad

    auto process = [&](int t0, bool diag) {
        __syncthreads();
        // ---- stage K tile: 128 t x 16 kq -> B-fragment layout, split ----
        {
            const float* kr = &g_k[(size_t)(b * S_ + t0 + KT) * 64 + kv * 16 + KH * 8];
            float4 ka = *(const float4*)kr;
            float4 kb = *(const float4*)(kr + 4);
            float kvv[8] = {ka.x, ka.y, ka.z, ka.w, kb.x, kb.y, kb.z, kb.w};
            int base = (KT >> 3) * 32 + (KT & 7) * 4;
            #pragma unroll
            for (int q = 0; q < 4; q++) {
                uint32_t hp, lp;
                split2(kvv[2 * q], kvv[2 * q + 1], hp, lp);
                int idx = (base + q) * 2 + KH;
                sKh[idx] = hp; sKl[idx] = lp;
            }
        }
        // ---- stage V tile: 128 t x 32 vb -> B-fragment layout (t pairs), split ----
        {
            const float* v0 = &g_v[(size_t)(b * S_ + t0 + 2 * Vtp) * 128 + kv * 32 + Vvbq];
            const float* v1 = v0 + 128;
            float4 va0 = *(const float4*)v0, va1 = *(const float4*)(v0 + 4);
            float4 vb0 = *(const float4*)v1, vb1 = *(const float4*)(v1 + 4);
            float x0[8] = {va0.x, va0.y, va0.z, va0.w, va1.x, va1.y, va1.z, va1.w};
            float x1[8] = {vb0.x, vb0.y, vb0.z, vb0.w, vb1.x, vb1.y, vb1.z, vb1.w};
            int ks = Vtp >> 3, breg = (Vtp >> 2) & 1, tg2 = Vtp & 3;
            #pragma unroll
            for (int j = 0; j < 8; j++) {
                int vb = Vvbq + j;
                uint32_t hp, lp;
                split2(x0[j], x1[j], hp, lp);
                int idx = ((ks * 4 + (vb >> 3)) * 32 + (vb & 7) * 4 + tg2) * 2 + breg;
                sVh[idx] = hp; sVl[idx] = lp;
            }
        }
        if (tid < 128)
            ssum[tid] = g_sumk[(size_t)(b * S_ + t0 + tid) * 4 + kv];
        __syncthreads();

        // ---- S = Q K^T : 3 split passes ----
        float sc[2][8][4];
        #pragma unroll
        for (int i = 0; i < 2; i++)
            #pragma unroll
            for (int j = 0; j < 8; j++)
                sc[i][j][0] = sc[i][j][1] = sc[i][j][2] = sc[i][j][3] = 0.f;

        uint32_t kb[8][2];
        #pragma unroll
        for (int j = 0; j < 8; j++) {
            uint2 v = *(const uint2*)&sKh[((nw * 8 + j) * 32 + lane) * 2];
            kb[j][0] = v.x; kb[j][1] = v.y;
        }
        #pragma unroll
        for (int i = 0; i < 2; i++)
            #pragma unroll
            for (int j = 0; j < 8; j++)
                mma16816(sc[i][j], qh[i], kb[j]);         // Qh*Kh
        #pragma unroll
        for (int i = 0; i < 2; i++)
            #pragma unroll
            for (int j = 0; j < 8; j++)
                mma16816(sc[i][j], ql[i], kb[j]);         // Ql*Kh
        #pragma unroll
        for (int j = 0; j < 8; j++) {
            uint2 v = *(const uint2*)&sKl[((nw * 8 + j) * 32 + lane) * 2];
            kb[j][0] = v.x; kb[j][1] = v.y;
        }
        #pragma unroll
        for (int i = 0; i < 2; i++)
            #pragma unroll
            for (int j = 0; j < 8; j++)
                mma16816(sc[i][j], qh[i], kb[j]);         // Qh*Kl

        // ---- softmax in fragments ----
        #pragma unroll
        for (int i = 0; i < 2; i++) {
            #pragma unroll
            for (int j = 0; j < 8; j++) {
                int tl = nw * 64 + j * 8 + 2 * tig;
                float2 sv = *(const float2*)&ssum[tl];
                float w0 = __expf(sc[i][j][0] - sv.x);
                float w1 = __expf(sc[i][j][1] - sv.y);
                float w2 = __expf(sc[i][j][2] - sv.x);
                float w3 = __expf(sc[i][j][3] - sv.y);
                if (diag) {
                    int tb = t0 + tl;
                    int s0 = m0 + mw * 32 + i * 16 + g, s1 = s0 + 8;
                    if (tb     > s0) w0 = 0.f;
                    if (tb + 1 > s0) w1 = 0.f;
                    if (tb     > s1) w2 = 0.f;
                    if (tb + 1 > s1) w3 = 0.f;
                }
                den[i][0] += w0 + w1;
                den[i][1] += w2 + w3;
                sc[i][j][0] = w0; sc[i][j][1] = w1;
                sc[i][j][2] = w2; sc[i][j][3] = w3;
            }
        }

        // ---- numer += w V : repack w in-registers, 3 split passes ----
        #pragma unroll
        for (int ks = 0; ks < 4; ks++) {
            uint32_t awh[2][4], awl[2][4];
            #pragma unroll
            for (int i = 0; i < 2; i++) {
                split2(sc[i][2*ks][0],   sc[i][2*ks][1],   awh[i][0], awl[i][0]);
                split2(sc[i][2*ks][2],   sc[i][2*ks][3],   awh[i][1], awl[i][1]);
                split2(sc[i][2*ks+1][0], sc[i][2*ks+1][1], awh[i][2], awl[i][2]);
                split2(sc[i][2*ks+1][2], sc[i][2*ks+1][3], awh[i][3], awl[i][3]);
            }
            #pragma unroll
            for (int jv = 0; jv < 4; jv++) {
                int vidx = (((nw * 4 + ks) * 4 + jv) * 32 + lane) * 2;
                uint2 bhv = *(const uint2*)&sVh[vidx];
                uint2 blv = *(const uint2*)&sVl[vidx];
                uint32_t bh[2] = {bhv.x, bhv.y};
                uint32_t bl[2] = {blv.x, blv.y};
                #pragma unroll
                for (int i = 0; i < 2; i++) {
                    mma16816(num[i][jv], awh[i], bh);     // wh*Vh
                    mma16816(num[i][jv], awl[i], bh);     // wl*Vh
                    mma16816(num[i][jv], awh[i], bl);     // wh*Vl
                }
            }
        }
    };

    for (int tile = 0; tile < qt; ++tile) process(tile * 128, false);
    process(qt * 128, true);

    // ---- reduce den over the 4 tig lanes (cols partitioned by tig) ----
    #pragma unroll
    for (int i = 0; i < 2; i++)
        #pragma unroll
        for (int hf = 0; hf < 2; hf++) {
            den[i][hf] += __shfl_xor_sync(0xFFFFFFFF, den[i][hf], 1);
            den[i][hf] += __shfl_xor_sync(0xFFFFFFFF, den[i][hf], 2);
        }

    // ---- cross-warp (nw) reduction via smem reuse ----
    __syncthreads();
    float4* rnum = (float4*)sm;               // [ (mw*32+lane)*8 + i*4+jv ]
    float4* rden = (float4*)(sm + 16384);     // [ mw*32+lane ]
    if (nw == 1) {
        #pragma unroll
        for (int i = 0; i < 2; i++)
            #pragma unroll
            for (int jv = 0; jv < 4; jv++)
                rnum[(mw * 32 + lane) * 8 + i * 4 + jv] =
                    make_float4(num[i][jv][0], num[i][jv][1], num[i][jv][2], num[i][jv][3]);
        rden[mw * 32 + lane] = make_float4(den[0][0], den[0][1], den[1][0], den[1][1]);
    }
    __syncthreads();
    if (nw == 0) {
        float4 dd = rden[mw * 32 + lane];
        den[0][0] += dd.x; den[0][1] += dd.y;
        den[1][0] += dd.z; den[1][1] += dd.w;
        #pragma unroll
        for (int i = 0; i < 2; i++) {
            float inv0 = 1.0f / den[i][0];
            float inv1 = 1.0f / den[i][1];
            int r0 = b * S_ + m0 + mw * 32 + i * 16 + g;
            float* o0 = &g_vh[(size_t)r0 * 512 + h * 32];
            #pragma unroll
            for (int jv = 0; jv < 4; jv++) {
                float4 p = rnum[(mw * 32 + lane) * 8 + i * 4 + jv];
                float n0 = (num[i][jv][0] + p.x) * inv0;
                float n1 = (num[i][jv][1] + p.y) * inv0;
                float n2 = (num[i][jv][2] + p.z) * inv1;
                float n3 = (num[i][jv][3] + p.w) * inv1;
                *(float2*)&o0[jv * 8 + 2 * tig]             = make_float2(n0, n1);
                *(float2*)&o0[8 * 512 + jv * 8 + 2 * tig]   = make_float2(n2, n3);
            }
        }
    }
}

// ---------------------------------------------------------------------------
// Kernel 4: mma.sync bf16 split-precision GEMM (unchanged from R11)
// C[4096,1024] = blend(g_vh)[4096,512] @ Wo[512,1024]
// ---------------------------------------------------------------------------
__global__ __launch_bounds__(256) void out_tc_kernel(
    const float* __restrict__ Wo, const float* __restrict__ e0,
    const float* __restrict__ e1, float* __restrict__ out)
{
    __shared__ uint32_t sAh[2 * 8 * 32 * 4];
    __shared__ uint32_t sAl[2 * 8 * 32 * 4];
    __shared__ uint32_t sBh[2 * 16 * 66];
    __shared__ uint32_t sBl[2 * 16 * 66];

    const int tid  = threadIdx.x;
    const int warp = tid >> 5, lane = tid & 31;
    const int n0 = blockIdx.x * 128;
    const int m0 = blockIdx.y * 128;
    const int mw = warp & 3;
    const int nw = warp >> 2;

    float c[2][8][4] = {};

    const int am  = tid >> 1;
    const int aks = tid & 1;
    const int bp  = tid >> 4;
    const int bnb = (tid & 15) * 8;

    for (int ch = 0; ch < 16; ch++) {
        const int k0 = ch * 32;
        __syncthreads();

        {
            const float* ar = &g_vh[(size_t)(m0 + am) * 512 + k0 + aks * 16];
            const float* z0 = &e0[k0 + aks * 16];
            const float* z1 = &e1[k0 + aks * 16];
            const int mt = am >> 4;
            const int mh = (am >> 3) & 1;
            const int lbase = (am & 7) * 4;
            #pragma unroll
            for (int q = 0; q < 4; q++) {
                float4 v  = *(const float4*)&ar[q * 4];
                float4 a0 = *(const float4*)&z0[q * 4];
                float4 a1 = *(const float4*)&z1[q * 4];
                float x0 = fmaf(a1.x - a0.x, v.x, a0.x);
                float x1 = fmaf(a1.y - a0.y, v.y, a0.y);
                float x2 = fmaf(a1.z - a0.z, v.z, a0.z);
                float x3 = fmaf(a1.w - a0.w, v.w, a0.w);
                #pragma unroll
                for (int hh = 0; hh < 2; hh++) {
                    int kk = q * 4 + hh * 2;
                    uint32_t hp, lp;
                    if (hh == 0) split2(x0, x1, hp, lp); else split2(x2, x3, hp, lp);
                    int reg    = ((kk >> 3) << 1) | mh;
                    int lane_t = lbase + ((kk & 7) >> 1);
                    int idx    = ((aks * 8 + mt) * 32 + lane_t) * 4 + reg;
                    sAh[idx] = hp; sAl[idx] = lp;
                }
            }
        }
        {
            const float* r0 = &Wo[(size_t)(k0 + 2 * bp) * 1024 + n0 + bnb];
            const float* r1 = r0 + 1024;
            float4 x0a = *(const float4*)&r0[0], x0b = *(const float4*)&r0[4];
            float4 x1a = *(const float4*)&r1[0], x1b = *(const float4*)&r1[4];
            const int kkl  = (2 * bp) & 15;
            const int ks   = bp >> 3;
            const int reg  = kkl >> 3;
            const int ltk  = (kkl & 7) >> 1;
            float v0[8] = {x0a.x, x0a.y, x0a.z, x0a.w, x0b.x, x0b.y, x0b.z, x0b.w};
            float v1[8] = {x1a.x, x1a.y, x1a.z, x1a.w, x1b.x, x1b.y, x1b.z, x1b.w};
            #pragma unroll
            for (int j = 0; j < 8; j++) {
                int n = bnb + j;
                uint32_t hp, lp;
                split2(v0[j], v1[j], hp, lp);
                int idx = (ks * 16 + (n >> 3)) * 66 + ((n & 7) * 4 + ltk) * 2 + reg;
                sBh[idx] = hp; sBl[idx] = lp;
            }
        }
        __syncthreads();

        #pragma unroll
        for (int ks = 0; ks < 2; ks++) {
            uint32_t ah[2][4], al[2][4], bh[8][2], bl[8][2];
            #pragma unroll
            for (int i = 0; i < 2; i++) {
                const uint4 v = *(const uint4*)&sAh[((ks * 8 + mw * 2 + i) * 32 + lane) * 4];
                ah[i][0] = v.x; ah[i][1] = v.y; ah[i][2] = v.z; ah[i][3] = v.w;
            }
            #pragma unroll
            for (int j = 0; j < 8; j++) {
                const uint2 v = *(const uint2*)&sBh[(ks * 16 + nw * 8 + j) * 66 + lane * 2];
                bh[j][0] = v.x; bh[j][1] = v.y;
            }
            #pragma unroll
            for (int i = 0; i < 2; i++)
                #pragma unroll
                for (int j = 0; j < 8; j++)
                    mma16816(c[i][j], ah[i], bh[j]);

            #pragma unroll
            for (int i = 0; i < 2; i++) {
                const uint4 v = *(const uint4*)&sAl[((ks * 8 + mw * 2 + i) * 32 + lane) * 4];
                al[i][0] = v.x; al[i][1] = v.y; al[i][2] = v.z; al[i][3] = v.w;
            }
            #pragma unroll
            for (int i = 0; i < 2; i++)
                #pragma unroll
                for (int j = 0; j < 8; j++)
                    mma16816(c[i][j], al[i], bh[j]);

            #pragma unroll
            for (int j = 0; j < 8; j++) {
                const uint2 v = *(const uint2*)&sBl[(ks * 16 + nw * 8 + j) * 66 + lane * 2];
                bl[j][0] = v.x; bl[j][1] = v.y;
            }
            #pragma unroll
            for (int i = 0; i < 2; i++)
                #pragma unroll
                for (int j = 0; j < 8; j++)
                    mma16816(c[i][j], ah[i], bl[j]);
        }
    }

    const int g  = lane >> 2, tg = lane & 3;
    #pragma unroll
    for (int i = 0; i < 2; i++) {
        #pragma unroll
        for (int j = 0; j < 8; j++) {
            int r0 = m0 + (mw * 2 + i) * 16 + g;
            int cc = n0 + (nw * 8 + j) * 8 + tg * 2;
            *(float2*)&out[(size_t)r0 * 1024 + cc] = make_float2(c[i][j][0], c[i][j][1]);
            *(float2*)&out[(size_t)(r0 + 8) * 1024 + cc] = make_float2(c[i][j][2], c[i][j][3]);
        }
    }
}

// ---------------------------------------------------------------------------
extern "C" void kernel_launch(void* const* d_in, const int* in_sizes, int n_in,
                              void* d_out, int out_size)
{
    const float* x  = (const float*)d_in[0];
    const float* Wq = (const float*)d_in[1];
    const float* Wk = (const float*)d_in[2];
    const float* Wv = (const float*)d_in[3];
    const float* Wo = (const float*)d_in[4];
    const float* e0 = (const float*)d_in[5];
    const float* e1 = (const float*)d_in[6];
    float* out = (float*)d_out;

    qkv_kernel<<<dim3(7, 32), 256>>>(x, Wq, Wk, Wv);
    sumk_kernel<<<64, 256>>>();
    attn_tc_kernel<<<dim3(S_ / 128, H_, B_), 256>>>();
    out_tc_kernel<<<dim3(8, 32), 256>>>(Wo, e0, e1, out);
}